// round 16
// baseline (speedup 1.0000x reference)
#include <cuda_runtime.h>
#include <math.h>

#define NN 2048
#define LL 1024
#define NROUND 2047
#define NSWEEP 10
#define NBLK 1024
#define TPB 128
#define NPOW 16

// ------------------- static device scratch (no runtime allocation) -------------------
__device__ float  d_A[NN * NN];      // H, then B^T for one-sided Jacobi (rows = columns of B)
__device__ float  d_pv[NN];          // power iteration vectors
__device__ float  d_pw[NN];
__device__ float  d_scal[1];         // 1/||w||
__device__ float  d_rho[1];          // ||w|| (spectral-norm estimate)
__device__ float  d_ev[NN];          // row norms (= lambda + c) for selection
__device__ int    d_sel[LL];         // indices of 1024 smallest eigenvalues
__device__ float  d_B2[LL * NN];     // selected (scaled) eigenvector rows
__device__ float  d_B[LL * LL];      // B[c][r] = B2[c][occ[r]]
__device__ double d_G[LL * LL];      // Gram of B   (fp64) -> Cholesky
__device__ double d_G2[LL * LL];     // Gram of B2  (fp64) -> Cholesky (scale/orthog. correction)
__device__ double d_accLog[1];       // +sum log L_ii (G)  - sum log L_ii (G2)
__device__ double d_accGauss[1];
__device__ double d_part[LL];
__device__ unsigned d_barCnt;
__device__ volatile unsigned d_barGen;

// ------------------- build H (symmetrized, as jnp.linalg.eigh does) -------------------
__device__ __forceinline__ float ph_dir(int i, int j, const float* Ph, const int* ivic,
                                        const float* sb, int da, int db) {
    int n1 = ivic[i * 4 + da];
    int n2 = ivic[i * 4 + db];
    if (j == n1 || j == n2) return (Ph[j] - Ph[i]) * sb[i * LL + j];
    return 0.f;
}

__global__ void build_H(const float* hm, const float* swm, const float* dwm,
                        const float* hv, const float* sv, const float* dv,
                        const float* g, const float* fS, const float* fD,
                        const float* X, const float* Y,
                        const int* ivic, const float* sb) {
    int t = blockIdx.x * blockDim.x + threadIdx.x;
    if (t >= NN * NN) return;
    int a = t / NN, b = t - a * NN;
    const float* h0m = hm;
    const float* h1m = hm + NN * NN;
    const float* h2m = hm + 2 * NN * NN;
    float base = -h1m[t] + hv[0] * h0m[t] + hv[1] * h2m[t]
               + sv[0] * swm[t] + dv[0] * dwm[t];

    int i = a & (LL - 1), j = b & (LL - 1);
    float pxs = 0.5f * (ph_dir(i, j, X, ivic, sb, 1, 3) + ph_dir(j, i, X, ivic, sb, 1, 3));
    float pys = 0.5f * (ph_dir(i, j, Y, ivic, sb, 0, 2) + ph_dir(j, i, Y, ivic, sb, 0, 2));
    float P = pxs + pys;
    float M = pxs - pys;

    float ph;
    bool ar = (a >= LL), br = (b >= LL);
    if (!ar && !br)      ph =  g[0] * P;
    else if (ar && br)   ph = -g[0] * P;
    else                 ph = fS[0] * P + fD[0] * M;

    d_A[t] = base + ph;
}

__global__ void zero_acc() {
    d_accLog[0] = 0.0;
    d_barCnt = 0;
    d_barGen = 0;
}

// ------------------- power iteration: estimate ||H||_2 -------------------
__global__ void pinit_k() {
    int i = blockIdx.x * 256 + threadIdx.x;
    if (i < NN) d_pv[i] = 1.0f + 0.001f * (float)(i % 97);
}

__global__ void gemv_k() {   // w = H v
    __shared__ float red[TPB];
    int row = blockIdx.x;
    const float* Ar = d_A + (size_t)row * NN;
    float acc = 0.f;
    for (int j = threadIdx.x; j < NN; j += TPB) acc += Ar[j] * d_pv[j];
    red[threadIdx.x] = acc;
    __syncthreads();
    for (int st = TPB / 2; st > 0; st >>= 1) {
        if (threadIdx.x < st) red[threadIdx.x] += red[threadIdx.x + st];
        __syncthreads();
    }
    if (threadIdx.x == 0) d_pw[row] = red[0];
}

__global__ void nrm_k() {    // d_scal = 1/||w||, d_rho = ||w||
    __shared__ double red[1024];
    int t = threadIdx.x;
    double v = (double)d_pw[t] * d_pw[t] + (double)d_pw[t + LL] * d_pw[t + LL];
    red[t] = v;
    __syncthreads();
    for (int st = 512; st > 0; st >>= 1) {
        if (t < st) red[t] += red[t + st];
        __syncthreads();
    }
    if (t == 0) {
        double n = sqrt(red[0]);
        d_rho[0] = (float)n;
        d_scal[0] = (float)(1.0 / (n > 1e-30 ? n : 1e-30));
    }
}

__global__ void scl_k() {    // v = w * scal
    int i = blockIdx.x * 256 + threadIdx.x;
    if (i < NN) d_pv[i] = d_pw[i] * d_scal[0];
}

__global__ void shift_k() {  // A += cI, c = 1.5*rho + 1
    int i = blockIdx.x * 256 + threadIdx.x;
    if (i < NN) {
        float c = 1.5f * d_rho[0] + 1.0f;
        d_A[(size_t)i * NN + i] += c;
    }
}

// ------------------- grid-wide software barrier (co-resident grid) -------------------
__device__ __forceinline__ void gsync(unsigned target) {
    __syncthreads();
    if (threadIdx.x == 0) {
        __threadfence();
        if (atomicAdd(&d_barCnt, 1u) == NBLK - 1) {
            d_barCnt = 0;
            __threadfence();
            d_barGen = target;
        } else {
            while (d_barGen < target) __nanosleep(32);
        }
    }
    __syncthreads();
}

// ------------------- persistent one-sided (Hestenes) Jacobi -------------------
// d_A holds B^T (row k = column k of B), B0 = H + cI (PSD). Each round, block i owns
// round-robin pair (p,q): load rows p,q to registers, fp64 dots (alpha,beta,gamma),
// rotate to zero gamma (= (B^TB)_pq = (A^2)_pq), store. At convergence row k = (lam_k+c)*v_k.
__global__ __launch_bounds__(TPB, 8) void jac1s_k() {
    __shared__ double sred[12];   // 4 warps x 3
    __shared__ double bc[3];
    unsigned bar = 0;
    int warp = threadIdx.x >> 5, lane = threadIdx.x & 31;

    for (int sw = 0; sw < NSWEEP; sw++)
    for (int r = 0; r < NROUND; r++) {
        int i = blockIdx.x;
        int p, q;
        if (i == 0) { p = r; q = NN - 1; }
        else { p = (i + r) % NROUND; q = (NROUND - i + r) % NROUND; }

        float4* P4 = (float4*)(d_A + (size_t)p * NN);
        float4* Q4 = (float4*)(d_A + (size_t)q * NN);

        float4 rp[4], rq[4];
        double a = 0.0, b = 0.0, g = 0.0;
        #pragma unroll
        for (int it = 0; it < 4; it++) {
            int j4 = threadIdx.x + it * TPB;
            float4 x = __ldcg(&P4[j4]);
            float4 y = __ldcg(&Q4[j4]);
            rp[it] = x; rq[it] = y;
            a += (double)x.x * x.x + (double)x.y * x.y + (double)x.z * x.z + (double)x.w * x.w;
            b += (double)y.x * y.x + (double)y.y * y.y + (double)y.z * y.z + (double)y.w * y.w;
            g += (double)x.x * y.x + (double)x.y * y.y + (double)x.z * y.z + (double)x.w * y.w;
        }
        // warp-level reduce
        #pragma unroll
        for (int off = 16; off > 0; off >>= 1) {
            a += __shfl_down_sync(0xffffffffu, a, off);
            b += __shfl_down_sync(0xffffffffu, b, off);
            g += __shfl_down_sync(0xffffffffu, g, off);
        }
        if (lane == 0) { sred[warp * 3] = a; sred[warp * 3 + 1] = b; sred[warp * 3 + 2] = g; }
        __syncthreads();
        if (threadIdx.x == 0) {
            bc[0] = sred[0] + sred[3] + sred[6] + sred[9];
            bc[1] = sred[1] + sred[4] + sred[7] + sred[10];
            bc[2] = sred[2] + sred[5] + sred[8] + sred[11];
        }
        __syncthreads();
        double alpha = bc[0], beta = bc[1], gamma = bc[2];

        float c = 1.f, s = 0.f;
        if (gamma != 0.0) {
            double tau = (beta - alpha) / (2.0 * gamma);
            double t = (tau >= 0.0 ? 1.0 : -1.0) / (fabs(tau) + sqrt(1.0 + tau * tau));
            double cc = rsqrt(1.0 + t * t);
            c = (float)cc;
            s = (float)(t * cc);
        }

        #pragma unroll
        for (int it = 0; it < 4; it++) {
            int j4 = threadIdx.x + it * TPB;
            float4 x = rp[it], y = rq[it];
            float4 np, nq;
            np.x = c * x.x - s * y.x;  nq.x = s * x.x + c * y.x;
            np.y = c * x.y - s * y.y;  nq.y = s * x.y + c * y.y;
            np.z = c * x.z - s * y.z;  nq.z = s * x.z + c * y.z;
            np.w = c * x.w - s * y.w;  nq.w = s * x.w + c * y.w;
            __stcg(&P4[j4], np);
            __stcg(&Q4[j4], nq);
        }
        gsync(++bar);
    }
}

// ------------------- row norms (= lambda + c), fp64 -------------------
__global__ void norm2_k() {
    __shared__ double red[TPB];
    int row = blockIdx.x;
    const float* Ar = d_A + (size_t)row * NN;
    double acc = 0.0;
    for (int j = threadIdx.x; j < NN; j += TPB) acc += (double)Ar[j] * Ar[j];
    red[threadIdx.x] = acc;
    __syncthreads();
    for (int st = TPB / 2; st > 0; st >>= 1) {
        if (threadIdx.x < st) red[threadIdx.x] += red[threadIdx.x + st];
        __syncthreads();
    }
    if (threadIdx.x == 0) d_ev[row] = (float)sqrt(red[0]);
}

// ------------------- select 1024 smallest (rank selection on norms) -------------------
__global__ void sel_k() {
    __shared__ float ev[NN];
    int t = threadIdx.x;  // 1024
    ev[t]      = d_ev[t];
    ev[t + LL] = d_ev[t + LL];
    __syncthreads();
    for (int kk = 0; kk < 2; kk++) {
        int k = t + kk * LL;
        float v = ev[k];
        int rank = 0;
        for (int j = 0; j < NN; j++) {
            float u = ev[j];
            rank += (u < v) || (u == v && j < k);
        }
        if (rank < LL) d_sel[rank] = k;
    }
}

// ------------------- gather selected (scaled) eigenvector rows -------------------
__global__ void gather2_k() {
    int t = blockIdx.x * 256 + threadIdx.x;
    if (t >= LL * NN) return;
    int c = t >> 11, k = t & (NN - 1);
    d_B2[t] = d_A[(size_t)d_sel[c] * NN + k];
}

__global__ void gatherB_k(const int* occ) {
    int t = blockIdx.x * 256 + threadIdx.x;
    if (t >= LL * LL) return;
    int c = t >> 10, rr = t & 1023;
    d_B[t] = d_B2[(size_t)c * NN + occ[rr]];
}

// ------------------- Gram = S * S^T (fp64); which=0: B (K=1024)->G, 1: B2 (K=2048)->G2
__global__ void gram_k(int which) {
    __shared__ float As[16][17], Bs[16][17];
    const float* S = which ? d_B2 : d_B;
    double* G = which ? d_G2 : d_G;
    int K = which ? NN : LL;
    int tx = threadIdx.x, ty = threadIdx.y;
    int row = blockIdx.y * 16 + ty;
    int col = blockIdx.x * 16 + tx;
    double acc = 0.0;
    for (int kk = 0; kk < K; kk += 16) {
        As[ty][tx] = S[(size_t)(blockIdx.y * 16 + ty) * K + kk + tx];
        Bs[ty][tx] = S[(size_t)(blockIdx.x * 16 + ty) * K + kk + tx];
        __syncthreads();
#pragma unroll
        for (int k2 = 0; k2 < 16; k2++)
            acc += (double)As[ty][k2] * (double)Bs[tx][k2];
        __syncthreads();
    }
    G[(size_t)row * LL + col] = acc;
}

// ------------------- blocked fp64 Cholesky (nb=64) -------------------
__global__ void potf2_k(int t, int which) {
    __shared__ double S[64][64];
    __shared__ double piv;
    double* G = which ? d_G2 : d_G;
    double sgn = which ? -1.0 : 1.0;
    int o = t * 64;
    int tid = threadIdx.x;  // 64 threads
    for (int r = 0; r < 64; r++) S[r][tid] = G[(size_t)(o + r) * LL + (o + tid)];
    __syncthreads();
    for (int k = 0; k < 64; k++) {
        if (tid == 0) {
            double dk = S[k][k];
            if (dk < 1e-250) dk = 1e-250;
            piv = sqrt(dk);
            S[k][k] = piv;
        }
        __syncthreads();
        double pv = piv;
        if (tid > k) S[tid][k] /= pv;
        __syncthreads();
        if (tid > k) {
            double lik = S[tid][k];
            for (int j = k + 1; j <= tid; j++) S[tid][j] -= lik * S[j][k];
        }
        __syncthreads();
    }
    if (tid == 0) {
        double ls = 0.0;
        for (int k = 0; k < 64; k++) ls += log(S[k][k]);
        d_accLog[0] += sgn * ls;   // sequential potf2 kernels: deterministic
    }
    for (int r = 0; r < 64; r++) G[(size_t)(o + r) * LL + (o + tid)] = S[r][tid];
}

__global__ void trsm_k(int t, int which) {
    __shared__ double L11[64][64];
    double* G = which ? d_G2 : d_G;
    int o = t * 64;
    int m0 = o + 64;
    int tid = threadIdx.x;  // 64
    {
        int r = tid;
        for (int c = 0; c < 64; c++) L11[r][c] = G[(size_t)(o + r) * LL + (o + c)];
    }
    __syncthreads();
    int row = m0 + blockIdx.x * 64 + tid;
    if (row < LL) {
        double xv[64];
        double* grow = &G[(size_t)row * LL + o];
        for (int c = 0; c < 64; c++) {
            double acc = grow[c];
            for (int k = 0; k < c; k++) acc -= xv[k] * L11[c][k];
            xv[c] = acc / L11[c][c];
        }
        for (int c = 0; c < 64; c++) grow[c] = xv[c];
    }
}

__global__ void syrk_k(int t, int which) {
    __shared__ double As[16][17], Bs[16][17];
    double* G = which ? d_G2 : d_G;
    int o = t * 64, m0 = o + 64;
    int tx = threadIdx.x, ty = threadIdx.y;
    int y = m0 + blockIdx.y * 16 + ty;
    int x = m0 + blockIdx.x * 16 + tx;
    double acc = 0.0;
    for (int kk = 0; kk < 64; kk += 16) {
        As[ty][tx] = G[(size_t)(m0 + blockIdx.y * 16 + ty) * LL + (o + kk + tx)];
        Bs[ty][tx] = G[(size_t)(m0 + blockIdx.x * 16 + ty) * LL + (o + kk + tx)];
        __syncthreads();
#pragma unroll
        for (int k2 = 0; k2 < 16; k2++) acc += As[ty][k2] * Bs[tx][k2];
        __syncthreads();
    }
    G[(size_t)y * LL + x] -= acc;
}

// ------------------- fused Jastrow + phonon quadratic forms -------------------
__global__ __launch_bounds__(256) void quad_k(const float* Sz, const float* X, const float* Y,
                                              const float* Js, const float* JcX, const float* JcY,
                                              const float* pXX, const float* pXY, const float* pYY,
                                              const float* sb) {
    __shared__ float sJs[289], sJcX[289], sJcY[289], sXX[289], sXY[289], sYY[289];
    __shared__ double red[256];
    int tid = threadIdx.x;
    for (int k = tid; k < 289; k += 256) {
        sJs[k]  = (k < 288) ? Js[k]  : 0.f;                    // pad_front=False
        sXX[k]  = (k < 288) ? pXX[k] : 0.f;
        sXY[k]  = (k < 288) ? pXY[k] : 0.f;
        sYY[k]  = (k < 288) ? pYY[k] : 0.f;
        sJcX[k] = (k == 0 || k >= 288) ? 0.f : JcX[k - 1];     // pad_front=True
        sJcY[k] = (k == 0 || k >= 288) ? 0.f : JcY[k - 1];
    }
    __syncthreads();
    int i = blockIdx.x;
    float xi = X[i], yi = Y[i], szi = Sz[i];
    int ix = i >> 5, iy = i & 31;
    double lsum = 0.0;
    for (int j = tid; j < LL; j += 256) {
        int jx = j >> 5, jy = j & 31;
        int dx = (jx - ix) & 31; if (dx > 16) dx = 32 - dx;
        int dy = (jy - iy) & 31; if (dy > 16) dy = 32 - dy;
        int idx = dx * 17 + dy;
        float sbij = sb[i * LL + j];
        float xj = X[j], yj = Y[j], szj = Sz[j];
        float v = szi * szj * (sJs[idx] + (sJcX[idx] * (xi - xj) + sJcY[idx] * (yi - yj)) * sbij)
                + xi * sXX[idx] * xj
                + (yi * xj + xi * yj) * sXY[idx]
                + yi * sYY[idx] * yj;
        lsum += (double)v;
    }
    red[tid] = lsum;
    __syncthreads();
    for (int st = 128; st > 0; st >>= 1) {
        if (tid < st) red[tid] += red[tid + st];
        __syncthreads();
    }
    if (tid == 0) d_part[i] = red[0];
}

__global__ void gauss_k(const float* X, const float* Y, const float* sx, const float* sy,
                        const float* zx, const float* zy, const float* xr, const float* yr) {
    __shared__ double red[1024];
    int t = threadIdx.x;
    float gx = X[t] - zx[0] * sx[t];
    float gy = Y[t] - zy[0] * sy[t];
    red[t] = -0.5 * (double)xr[0] * (double)gx * (double)gx
             - 0.5 * (double)yr[0] * (double)gy * (double)gy;
    __syncthreads();
    for (int st = 512; st > 0; st >>= 1) {
        if (t < st) red[t] += red[t + st];
        __syncthreads();
    }
    if (t == 0) d_accGauss[0] = red[0];
}

__global__ void final_k(float* out) {
    __shared__ double red[1024];
    int t = threadIdx.x;
    red[t] = d_part[t];
    __syncthreads();
    for (int st = 512; st > 0; st >>= 1) {
        if (t < st) red[t] += red[t + st];
        __syncthreads();
    }
    if (t == 0) out[0] = (float)(red[0] + d_accGauss[0] + d_accLog[0]);
}

// ------------------- launch -------------------
extern "C" void kernel_launch(void* const* d_in, const int* in_sizes, int n_in,
                              void* d_out, int out_size) {
    const int*   occ  = (const int*)d_in[0];
    // d_in[1] = xloc (unused by reference)
    const float* Sz   = (const float*)d_in[2];
    const float* X    = (const float*)d_in[3];
    const float* Y    = (const float*)d_in[4];
    const float* hv   = (const float*)d_in[5];
    const float* sv   = (const float*)d_in[6];
    const float* dv   = (const float*)d_in[7];
    const float* Js   = (const float*)d_in[8];
    const float* JcX  = (const float*)d_in[9];
    const float* JcY  = (const float*)d_in[10];
    const float* pXX  = (const float*)d_in[11];
    const float* pXY  = (const float*)d_in[12];
    const float* pYY  = (const float*)d_in[13];
    const float* g    = (const float*)d_in[14];
    const float* fS   = (const float*)d_in[15];
    const float* fD   = (const float*)d_in[16];
    const float* zx   = (const float*)d_in[17];
    const float* zy   = (const float*)d_in[18];
    const float* xr   = (const float*)d_in[19];
    const float* yr   = (const float*)d_in[20];
    const float* hm   = (const float*)d_in[21];
    const float* swm  = (const float*)d_in[22];
    const float* dwm  = (const float*)d_in[23];
    const int*   ivic = (const int*)d_in[24];
    const float* sb   = (const float*)d_in[25];
    const float* sx   = (const float*)d_in[26];
    const float* sy   = (const float*)d_in[27];
    float* out = (float*)d_out;

    int nb = (NN * NN + 255) / 256;
    build_H<<<nb, 256>>>(hm, swm, dwm, hv, sv, dv, g, fS, fD, X, Y, ivic, sb);
    zero_acc<<<1, 1>>>();

    // power iteration: rho ~ ||H||_2, then shift A += (1.5 rho + 1) I  -> PSD
    pinit_k<<<NN / 256, 256>>>();
    for (int it = 0; it < NPOW; it++) {
        gemv_k<<<NN, TPB>>>();
        nrm_k<<<1, 1024>>>();
        scl_k<<<NN / 256, 256>>>();
    }
    shift_k<<<NN / 256, 256>>>();

    // persistent one-sided Jacobi: all NSWEEP x NROUND rounds, 1 barrier/round
    jac1s_k<<<NBLK, TPB>>>();

    norm2_k<<<NN, TPB>>>();
    sel_k<<<1, 1024>>>();
    gather2_k<<<(LL * NN + 255) / 256, 256>>>();
    gatherB_k<<<(LL * LL + 255) / 256, 256>>>(occ);
    gram_k<<<dim3(64, 64), dim3(16, 16)>>>(0);
    gram_k<<<dim3(64, 64), dim3(16, 16)>>>(1);

    for (int which = 0; which < 2; which++) {
        for (int t = 0; t < 16; t++) {
            potf2_k<<<1, 64>>>(t, which);
            int m = LL - (t + 1) * 64;
            if (m > 0) {
                trsm_k<<<m / 64, 64>>>(t, which);
                syrk_k<<<dim3(m / 16, m / 16), dim3(16, 16)>>>(t, which);
            }
        }
    }

    quad_k<<<LL, 256>>>(Sz, X, Y, Js, JcX, JcY, pXX, pXY, pYY, sb);
    gauss_k<<<1, 1024>>>(X, Y, sx, sy, zx, zy, xr, yr);
    final_k<<<1, 1024>>>(out);
}

// round 17
// speedup vs baseline: 2.5957x; 2.5957x over previous
#include <cuda_runtime.h>
#include <math.h>

#define NN 2048
#define LL 1024
#define NROUND 2047
#define NSWEEP 10
#define NBLK 1024
#define TPB 128
#define NPOW 16

// ------------------- static device scratch (no runtime allocation) -------------------
__device__ float  d_A[NN * NN];      // H, then B^T for one-sided Jacobi (rows = columns of B)
__device__ float  d_pv[NN];          // power iteration vectors
__device__ float  d_pw[NN];
__device__ float  d_scal[1];         // 1/||w||
__device__ float  d_rho[1];          // ||w|| (spectral-norm estimate)
__device__ float  d_ev[NN];          // row norms (= lambda + c) for selection
__device__ int    d_sel[LL];         // indices of 1024 smallest eigenvalues
__device__ float  d_B2[LL * NN];     // selected (scaled) eigenvector rows
__device__ float  d_B[LL * LL];      // B[c][r] = B2[c][occ[r]]
__device__ double d_G[LL * LL];      // Gram of B   (fp64) -> Cholesky
__device__ double d_G2[LL * LL];     // Gram of B2  (fp64) -> Cholesky (scale/orthog. correction)
__device__ double d_accLog[1];       // +sum log L_ii (G)  - sum log L_ii (G2)
__device__ double d_accGauss[1];
__device__ double d_part[LL];
__device__ unsigned d_barCnt;
__device__ volatile unsigned d_barGen;

// ------------------- build H (symmetrized, as jnp.linalg.eigh does) -------------------
__device__ __forceinline__ float ph_dir(int i, int j, const float* Ph, const int* ivic,
                                        const float* sb, int da, int db) {
    int n1 = ivic[i * 4 + da];
    int n2 = ivic[i * 4 + db];
    if (j == n1 || j == n2) return (Ph[j] - Ph[i]) * sb[i * LL + j];
    return 0.f;
}

__global__ void build_H(const float* hm, const float* swm, const float* dwm,
                        const float* hv, const float* sv, const float* dv,
                        const float* g, const float* fS, const float* fD,
                        const float* X, const float* Y,
                        const int* ivic, const float* sb) {
    int t = blockIdx.x * blockDim.x + threadIdx.x;
    if (t >= NN * NN) return;
    int a = t / NN, b = t - a * NN;
    const float* h0m = hm;
    const float* h1m = hm + NN * NN;
    const float* h2m = hm + 2 * NN * NN;
    float base = -h1m[t] + hv[0] * h0m[t] + hv[1] * h2m[t]
               + sv[0] * swm[t] + dv[0] * dwm[t];

    int i = a & (LL - 1), j = b & (LL - 1);
    float pxs = 0.5f * (ph_dir(i, j, X, ivic, sb, 1, 3) + ph_dir(j, i, X, ivic, sb, 1, 3));
    float pys = 0.5f * (ph_dir(i, j, Y, ivic, sb, 0, 2) + ph_dir(j, i, Y, ivic, sb, 0, 2));
    float P = pxs + pys;
    float M = pxs - pys;

    float ph;
    bool ar = (a >= LL), br = (b >= LL);
    if (!ar && !br)      ph =  g[0] * P;
    else if (ar && br)   ph = -g[0] * P;
    else                 ph = fS[0] * P + fD[0] * M;

    d_A[t] = base + ph;
}

__global__ void zero_acc() {
    d_accLog[0] = 0.0;
    d_barCnt = 0;
    d_barGen = 0;
}

// ------------------- power iteration: estimate ||H||_2 -------------------
__global__ void pinit_k() {
    int i = blockIdx.x * 256 + threadIdx.x;
    if (i < NN) d_pv[i] = 1.0f + 0.001f * (float)(i % 97);
}

__global__ void gemv_k() {   // w = H v
    __shared__ float red[TPB];
    int row = blockIdx.x;
    const float* Ar = d_A + (size_t)row * NN;
    float acc = 0.f;
    for (int j = threadIdx.x; j < NN; j += TPB) acc += Ar[j] * d_pv[j];
    red[threadIdx.x] = acc;
    __syncthreads();
    for (int st = TPB / 2; st > 0; st >>= 1) {
        if (threadIdx.x < st) red[threadIdx.x] += red[threadIdx.x + st];
        __syncthreads();
    }
    if (threadIdx.x == 0) d_pw[row] = red[0];
}

__global__ void nrm_k() {    // d_scal = 1/||w||, d_rho = ||w||
    __shared__ double red[1024];
    int t = threadIdx.x;
    double v = (double)d_pw[t] * d_pw[t] + (double)d_pw[t + LL] * d_pw[t + LL];
    red[t] = v;
    __syncthreads();
    for (int st = 512; st > 0; st >>= 1) {
        if (t < st) red[t] += red[t + st];
        __syncthreads();
    }
    if (t == 0) {
        double n = sqrt(red[0]);
        d_rho[0] = (float)n;
        d_scal[0] = (float)(1.0 / (n > 1e-30 ? n : 1e-30));
    }
}

__global__ void scl_k() {    // v = w * scal
    int i = blockIdx.x * 256 + threadIdx.x;
    if (i < NN) d_pv[i] = d_pw[i] * d_scal[0];
}

__global__ void shift_k() {  // A += cI, c = 1.5*rho + 1
    int i = blockIdx.x * 256 + threadIdx.x;
    if (i < NN) {
        float c = 1.5f * d_rho[0] + 1.0f;
        d_A[(size_t)i * NN + i] += c;
    }
}

// ------------------- grid-wide software barrier (co-resident grid) -------------------
__device__ __forceinline__ void gsync(unsigned target) {
    __syncthreads();
    if (threadIdx.x == 0) {
        __threadfence();
        if (atomicAdd(&d_barCnt, 1u) == NBLK - 1) {
            d_barCnt = 0;
            __threadfence();
            d_barGen = target;
        } else {
            while (d_barGen < target) __nanosleep(32);
        }
    }
    __syncthreads();
}

// ------------------- persistent one-sided (Hestenes) Jacobi -------------------
// d_A holds B^T (row k = column k of B), B0 = H + cI (PSD). Each round, block i owns
// round-robin pair (p,q): load rows p,q to registers, fp32 FMA dots (alpha,beta,gamma),
// warp-shuffle fp32 reduce; thread 0 computes the rotation ONCE in fp64 and broadcasts
// (c,s) via smem. Rotate in registers, store. At convergence row k = (lam_k+c)*v_k.
__global__ __launch_bounds__(TPB, 8) void jac1s_k() {
    __shared__ float sred[12];   // 4 warps x 3
    __shared__ float bcs[2];
    unsigned bar = 0;
    int warp = threadIdx.x >> 5, lane = threadIdx.x & 31;

    for (int sw = 0; sw < NSWEEP; sw++)
    for (int r = 0; r < NROUND; r++) {
        int i = blockIdx.x;
        int p, q;
        if (i == 0) { p = r; q = NN - 1; }
        else { p = (i + r) % NROUND; q = (NROUND - i + r) % NROUND; }

        float4* P4 = (float4*)(d_A + (size_t)p * NN);
        float4* Q4 = (float4*)(d_A + (size_t)q * NN);

        float4 rp[4], rq[4];
        float a = 0.f, b = 0.f, g = 0.f;
        #pragma unroll
        for (int it = 0; it < 4; it++) {
            int j4 = threadIdx.x + it * TPB;
            float4 x = __ldcg(&P4[j4]);
            float4 y = __ldcg(&Q4[j4]);
            rp[it] = x; rq[it] = y;
            a = fmaf(x.x, x.x, a); a = fmaf(x.y, x.y, a);
            a = fmaf(x.z, x.z, a); a = fmaf(x.w, x.w, a);
            b = fmaf(y.x, y.x, b); b = fmaf(y.y, y.y, b);
            b = fmaf(y.z, y.z, b); b = fmaf(y.w, y.w, b);
            g = fmaf(x.x, y.x, g); g = fmaf(x.y, y.y, g);
            g = fmaf(x.z, y.z, g); g = fmaf(x.w, y.w, g);
        }
        // fp32 warp-level reduce
        #pragma unroll
        for (int off = 16; off > 0; off >>= 1) {
            a += __shfl_down_sync(0xffffffffu, a, off);
            b += __shfl_down_sync(0xffffffffu, b, off);
            g += __shfl_down_sync(0xffffffffu, g, off);
        }
        if (lane == 0) { sred[warp * 3] = a; sred[warp * 3 + 1] = b; sred[warp * 3 + 2] = g; }
        __syncthreads();
        // thread 0 computes the rotation ONCE (fp64), broadcasts (c,s)
        if (threadIdx.x == 0) {
            double alpha = (double)sred[0] + sred[3] + sred[6] + sred[9];
            double beta  = (double)sred[1] + sred[4] + sred[7] + sred[10];
            double gamma = (double)sred[2] + sred[5] + sred[8] + sred[11];
            float c = 1.f, s = 0.f;
            if (gamma != 0.0) {
                double tau = (beta - alpha) / (2.0 * gamma);
                double t = (tau >= 0.0 ? 1.0 : -1.0) / (fabs(tau) + sqrt(1.0 + tau * tau));
                double cc = rsqrt(1.0 + t * t);
                c = (float)cc;
                s = (float)(t * cc);
            }
            bcs[0] = c; bcs[1] = s;
        }
        __syncthreads();
        float c = bcs[0], s = bcs[1];

        #pragma unroll
        for (int it = 0; it < 4; it++) {
            int j4 = threadIdx.x + it * TPB;
            float4 x = rp[it], y = rq[it];
            float4 np, nq;
            np.x = c * x.x - s * y.x;  nq.x = s * x.x + c * y.x;
            np.y = c * x.y - s * y.y;  nq.y = s * x.y + c * y.y;
            np.z = c * x.z - s * y.z;  nq.z = s * x.z + c * y.z;
            np.w = c * x.w - s * y.w;  nq.w = s * x.w + c * y.w;
            __stcg(&P4[j4], np);
            __stcg(&Q4[j4], nq);
        }
        gsync(++bar);
    }
}

// ------------------- row norms (= lambda + c), fp64 -------------------
__global__ void norm2_k() {
    __shared__ double red[TPB];
    int row = blockIdx.x;
    const float* Ar = d_A + (size_t)row * NN;
    double acc = 0.0;
    for (int j = threadIdx.x; j < NN; j += TPB) acc += (double)Ar[j] * Ar[j];
    red[threadIdx.x] = acc;
    __syncthreads();
    for (int st = TPB / 2; st > 0; st >>= 1) {
        if (threadIdx.x < st) red[threadIdx.x] += red[threadIdx.x + st];
        __syncthreads();
    }
    if (threadIdx.x == 0) d_ev[row] = (float)sqrt(red[0]);
}

// ------------------- select 1024 smallest (rank selection on norms) -------------------
__global__ void sel_k() {
    __shared__ float ev[NN];
    int t = threadIdx.x;  // 1024
    ev[t]      = d_ev[t];
    ev[t + LL] = d_ev[t + LL];
    __syncthreads();
    for (int kk = 0; kk < 2; kk++) {
        int k = t + kk * LL;
        float v = ev[k];
        int rank = 0;
        for (int j = 0; j < NN; j++) {
            float u = ev[j];
            rank += (u < v) || (u == v && j < k);
        }
        if (rank < LL) d_sel[rank] = k;
    }
}

// ------------------- gather selected (scaled) eigenvector rows -------------------
__global__ void gather2_k() {
    int t = blockIdx.x * 256 + threadIdx.x;
    if (t >= LL * NN) return;
    int c = t >> 11, k = t & (NN - 1);
    d_B2[t] = d_A[(size_t)d_sel[c] * NN + k];
}

__global__ void gatherB_k(const int* occ) {
    int t = blockIdx.x * 256 + threadIdx.x;
    if (t >= LL * LL) return;
    int c = t >> 10, rr = t & 1023;
    d_B[t] = d_B2[(size_t)c * NN + occ[rr]];
}

// ------------------- Gram = S * S^T (fp64); which=0: B (K=1024)->G, 1: B2 (K=2048)->G2
__global__ void gram_k(int which) {
    __shared__ float As[16][17], Bs[16][17];
    const float* S = which ? d_B2 : d_B;
    double* G = which ? d_G2 : d_G;
    int K = which ? NN : LL;
    int tx = threadIdx.x, ty = threadIdx.y;
    int row = blockIdx.y * 16 + ty;
    int col = blockIdx.x * 16 + tx;
    double acc = 0.0;
    for (int kk = 0; kk < K; kk += 16) {
        As[ty][tx] = S[(size_t)(blockIdx.y * 16 + ty) * K + kk + tx];
        Bs[ty][tx] = S[(size_t)(blockIdx.x * 16 + ty) * K + kk + tx];
        __syncthreads();
#pragma unroll
        for (int k2 = 0; k2 < 16; k2++)
            acc += (double)As[ty][k2] * (double)Bs[tx][k2];
        __syncthreads();
    }
    G[(size_t)row * LL + col] = acc;
}

// ------------------- blocked fp64 Cholesky (nb=64) -------------------
__global__ void potf2_k(int t, int which) {
    __shared__ double S[64][64];
    __shared__ double piv;
    double* G = which ? d_G2 : d_G;
    double sgn = which ? -1.0 : 1.0;
    int o = t * 64;
    int tid = threadIdx.x;  // 64 threads
    for (int r = 0; r < 64; r++) S[r][tid] = G[(size_t)(o + r) * LL + (o + tid)];
    __syncthreads();
    for (int k = 0; k < 64; k++) {
        if (tid == 0) {
            double dk = S[k][k];
            if (dk < 1e-250) dk = 1e-250;
            piv = sqrt(dk);
            S[k][k] = piv;
        }
        __syncthreads();
        double pv = piv;
        if (tid > k) S[tid][k] /= pv;
        __syncthreads();
        if (tid > k) {
            double lik = S[tid][k];
            for (int j = k + 1; j <= tid; j++) S[tid][j] -= lik * S[j][k];
        }
        __syncthreads();
    }
    if (tid == 0) {
        double ls = 0.0;
        for (int k = 0; k < 64; k++) ls += log(S[k][k]);
        d_accLog[0] += sgn * ls;   // sequential potf2 kernels: deterministic
    }
    for (int r = 0; r < 64; r++) G[(size_t)(o + r) * LL + (o + tid)] = S[r][tid];
}

__global__ void trsm_k(int t, int which) {
    __shared__ double L11[64][64];
    double* G = which ? d_G2 : d_G;
    int o = t * 64;
    int m0 = o + 64;
    int tid = threadIdx.x;  // 64
    {
        int r = tid;
        for (int c = 0; c < 64; c++) L11[r][c] = G[(size_t)(o + r) * LL + (o + c)];
    }
    __syncthreads();
    int row = m0 + blockIdx.x * 64 + tid;
    if (row < LL) {
        double xv[64];
        double* grow = &G[(size_t)row * LL + o];
        for (int c = 0; c < 64; c++) {
            double acc = grow[c];
            for (int k = 0; k < c; k++) acc -= xv[k] * L11[c][k];
            xv[c] = acc / L11[c][c];
        }
        for (int c = 0; c < 64; c++) grow[c] = xv[c];
    }
}

__global__ void syrk_k(int t, int which) {
    __shared__ double As[16][17], Bs[16][17];
    double* G = which ? d_G2 : d_G;
    int o = t * 64, m0 = o + 64;
    int tx = threadIdx.x, ty = threadIdx.y;
    int y = m0 + blockIdx.y * 16 + ty;
    int x = m0 + blockIdx.x * 16 + tx;
    double acc = 0.0;
    for (int kk = 0; kk < 64; kk += 16) {
        As[ty][tx] = G[(size_t)(m0 + blockIdx.y * 16 + ty) * LL + (o + kk + tx)];
        Bs[ty][tx] = G[(size_t)(m0 + blockIdx.x * 16 + ty) * LL + (o + kk + tx)];
        __syncthreads();
#pragma unroll
        for (int k2 = 0; k2 < 16; k2++) acc += As[ty][k2] * Bs[tx][k2];
        __syncthreads();
    }
    G[(size_t)y * LL + x] -= acc;
}

// ------------------- fused Jastrow + phonon quadratic forms -------------------
__global__ __launch_bounds__(256) void quad_k(const float* Sz, const float* X, const float* Y,
                                              const float* Js, const float* JcX, const float* JcY,
                                              const float* pXX, const float* pXY, const float* pYY,
                                              const float* sb) {
    __shared__ float sJs[289], sJcX[289], sJcY[289], sXX[289], sXY[289], sYY[289];
    __shared__ double red[256];
    int tid = threadIdx.x;
    for (int k = tid; k < 289; k += 256) {
        sJs[k]  = (k < 288) ? Js[k]  : 0.f;                    // pad_front=False
        sXX[k]  = (k < 288) ? pXX[k] : 0.f;
        sXY[k]  = (k < 288) ? pXY[k] : 0.f;
        sYY[k]  = (k < 288) ? pYY[k] : 0.f;
        sJcX[k] = (k == 0 || k >= 288) ? 0.f : JcX[k - 1];     // pad_front=True
        sJcY[k] = (k == 0 || k >= 288) ? 0.f : JcY[k - 1];
    }
    __syncthreads();
    int i = blockIdx.x;
    float xi = X[i], yi = Y[i], szi = Sz[i];
    int ix = i >> 5, iy = i & 31;
    double lsum = 0.0;
    for (int j = tid; j < LL; j += 256) {
        int jx = j >> 5, jy = j & 31;
        int dx = (jx - ix) & 31; if (dx > 16) dx = 32 - dx;
        int dy = (jy - iy) & 31; if (dy > 16) dy = 32 - dy;
        int idx = dx * 17 + dy;
        float sbij = sb[i * LL + j];
        float xj = X[j], yj = Y[j], szj = Sz[j];
        float v = szi * szj * (sJs[idx] + (sJcX[idx] * (xi - xj) + sJcY[idx] * (yi - yj)) * sbij)
                + xi * sXX[idx] * xj
                + (yi * xj + xi * yj) * sXY[idx]
                + yi * sYY[idx] * yj;
        lsum += (double)v;
    }
    red[tid] = lsum;
    __syncthreads();
    for (int st = 128; st > 0; st >>= 1) {
        if (tid < st) red[tid] += red[tid + st];
        __syncthreads();
    }
    if (tid == 0) d_part[i] = red[0];
}

__global__ void gauss_k(const float* X, const float* Y, const float* sx, const float* sy,
                        const float* zx, const float* zy, const float* xr, const float* yr) {
    __shared__ double red[1024];
    int t = threadIdx.x;
    float gx = X[t] - zx[0] * sx[t];
    float gy = Y[t] - zy[0] * sy[t];
    red[t] = -0.5 * (double)xr[0] * (double)gx * (double)gx
             - 0.5 * (double)yr[0] * (double)gy * (double)gy;
    __syncthreads();
    for (int st = 512; st > 0; st >>= 1) {
        if (t < st) red[t] += red[t + st];
        __syncthreads();
    }
    if (t == 0) d_accGauss[0] = red[0];
}

__global__ void final_k(float* out) {
    __shared__ double red[1024];
    int t = threadIdx.x;
    red[t] = d_part[t];
    __syncthreads();
    for (int st = 512; st > 0; st >>= 1) {
        if (t < st) red[t] += red[t + st];
        __syncthreads();
    }
    if (t == 0) out[0] = (float)(red[0] + d_accGauss[0] + d_accLog[0]);
}

// ------------------- launch -------------------
extern "C" void kernel_launch(void* const* d_in, const int* in_sizes, int n_in,
                              void* d_out, int out_size) {
    const int*   occ  = (const int*)d_in[0];
    // d_in[1] = xloc (unused by reference)
    const float* Sz   = (const float*)d_in[2];
    const float* X    = (const float*)d_in[3];
    const float* Y    = (const float*)d_in[4];
    const float* hv   = (const float*)d_in[5];
    const float* sv   = (const float*)d_in[6];
    const float* dv   = (const float*)d_in[7];
    const float* Js   = (const float*)d_in[8];
    const float* JcX  = (const float*)d_in[9];
    const float* JcY  = (const float*)d_in[10];
    const float* pXX  = (const float*)d_in[11];
    const float* pXY  = (const float*)d_in[12];
    const float* pYY  = (const float*)d_in[13];
    const float* g    = (const float*)d_in[14];
    const float* fS   = (const float*)d_in[15];
    const float* fD   = (const float*)d_in[16];
    const float* zx   = (const float*)d_in[17];
    const float* zy   = (const float*)d_in[18];
    const float* xr   = (const float*)d_in[19];
    const float* yr   = (const float*)d_in[20];
    const float* hm   = (const float*)d_in[21];
    const float* swm  = (const float*)d_in[22];
    const float* dwm  = (const float*)d_in[23];
    const int*   ivic = (const int*)d_in[24];
    const float* sb   = (const float*)d_in[25];
    const float* sx   = (const float*)d_in[26];
    const float* sy   = (const float*)d_in[27];
    float* out = (float*)d_out;

    int nb = (NN * NN + 255) / 256;
    build_H<<<nb, 256>>>(hm, swm, dwm, hv, sv, dv, g, fS, fD, X, Y, ivic, sb);
    zero_acc<<<1, 1>>>();

    // power iteration: rho ~ ||H||_2, then shift A += (1.5 rho + 1) I  -> PSD
    pinit_k<<<NN / 256, 256>>>();
    for (int it = 0; it < NPOW; it++) {
        gemv_k<<<NN, TPB>>>();
        nrm_k<<<1, 1024>>>();
        scl_k<<<NN / 256, 256>>>();
    }
    shift_k<<<NN / 256, 256>>>();

    // persistent one-sided Jacobi: all NSWEEP x NROUND rounds, 1 barrier/round
    jac1s_k<<<NBLK, TPB>>>();

    norm2_k<<<NN, TPB>>>();
    sel_k<<<1, 1024>>>();
    gather2_k<<<(LL * NN + 255) / 256, 256>>>();
    gatherB_k<<<(LL * LL + 255) / 256, 256>>>(occ);
    gram_k<<<dim3(64, 64), dim3(16, 16)>>>(0);
    gram_k<<<dim3(64, 64), dim3(16, 16)>>>(1);

    for (int which = 0; which < 2; which++) {
        for (int t = 0; t < 16; t++) {
            potf2_k<<<1, 64>>>(t, which);
            int m = LL - (t + 1) * 64;
            if (m > 0) {
                trsm_k<<<m / 64, 64>>>(t, which);
                syrk_k<<<dim3(m / 16, m / 16), dim3(16, 16)>>>(t, which);
            }
        }
    }

    quad_k<<<LL, 256>>>(Sz, X, Y, Js, JcX, JcY, pXX, pXY, pYY, sb);
    gauss_k<<<1, 1024>>>(X, Y, sx, sy, zx, zy, xr, yr);
    final_k<<<1, 1024>>>(out);
}